// round 14
// baseline (speedup 1.0000x reference)
#include <cuda_runtime.h>

// MacUnit: out[b, 2*ic+k] = attention[2*ic+k] * f3(data[b, ic])
// f3 = 3 iterations of x += step(x)/3 (tanh-indexed piecewise-linear trig).
//
// R14: map kernel identical to R12 (best measured: 35.0us, DRAM 52%).
// Build kernel rewritten with a register-resident segment table (lanes 0..17,
// SHFL.IDX lookups) so each exact eval has NO dependent gmem loads -- R13
// showed the build kernel + launch overhead is ~8us of the bench total.
// Table: (value,delta) float2, [-4,4], h=1/1024, 64KB smem, 2 CTAs/SM.

#define NUM_POINTS 17
#define TAB_INTERVALS 8192               // h = 1/1024 over [-4,4]
#define TAB_SCALE     1024.0f
#define TAB_H         (1.0f / 1024.0f)
#define TAB_BYTES     (TAB_INTERVALS * 8)   // 65536 B of float2

__device__ float2 g_tab[TAB_INTERVALS];

// ---------------------------------------------------------------------------
// Kernel 1: build (value, delta) pair table. Exact f3 with the segment table
// in registers of lanes 0..17 (warp-shuffle lookup; no gmem in the loop).
// ---------------------------------------------------------------------------
__global__ __launch_bounds__(256)
void build_table_kernel(const float* __restrict__ angles,
                        const float* __restrict__ velocity,
                        const float* __restrict__ coeff,
                        const float* __restrict__ bias)
{
    const int lane = threadIdx.x & 31;

    // Per-warp register-resident segment table (bgn = lane - 8).
    float r_vb3 = 0.f, r_dv3 = 0.f, r_ab = 0.f, r_da = 0.f;
    if (lane < 18) {
        int bgn = lane - 8;
        int end = bgn + 1;
        int bw = bgn < 0 ? bgn + NUM_POINTS : bgn;    // torch negative wrap
        int ew = end < 0 ? end + NUM_POINTS : end;
        float vb = __ldg(&velocity[bw]) * (1.0f / 3.0f);
        float ve = __ldg(&velocity[ew]) * (1.0f / 3.0f);
        r_vb3 = vb;
        r_dv3 = ve - vb;
        r_ab  = __ldg(&angles[bw]);
        r_da  = __ldg(&angles[ew]) - r_ab;
    }

    const float c2l = __ldg(coeff) * 2.8853900817779268f;   // 2*log2(e)*c
    const float b2l = __ldg(bias)  * 2.8853900817779268f;

    const int i = blockIdx.x * 256 + threadIdx.x;
    if (i >= TAB_INTERVALS) return;

    float v[2];
    #pragma unroll
    for (int q = 0; q < 2; q++) {
        float x = fmaf((float)(i + q), TAB_H, -4.0f);       // exact grid point
        #pragma unroll
        for (int s = 0; s < 3; s++) {
            float e;
            asm("ex2.approx.f32 %0, %1;" : "=f"(e) : "f"(fmaf(x, c2l, b2l)));
            float r;
            asm("rcp.approx.f32 %0, %1;" : "=f"(r) : "f"(e + 1.0f));
            float u = fmaf(r, -17.0f, 17.5f);   // index + 8, in (0.5, 17.5)
            int   si = (int)u;                  // trunc == floor (u > 0)
            float pos = u - (float)si;
            float vb = __shfl_sync(0xffffffffu, r_vb3, si);
            float dv = __shfl_sync(0xffffffffu, r_dv3, si);
            float ab = __shfl_sync(0xffffffffu, r_ab,  si);
            float da = __shfl_sync(0xffffffffu, r_da,  si);
            float velo3 = fmaf(pos, dv, vb);
            float ang   = fmaf(pos, da, ab);
            float sn, cs;
            __sincosf(ang, &sn, &cs);
            x = fmaf(x, fmaf(velo3, sn, 1.0f), velo3 * cs);
        }
        v[q] = x;
    }
    g_tab[i] = make_float2(v[0], v[1] - v[0]);
}

// Exact f3 via gmem tables (rare |x|>=4 path in the map kernel only).
__device__ __forceinline__ float f3_exact_g(float x, float c2l, float b2l,
                                            const float* __restrict__ angles,
                                            const float* __restrict__ velocity)
{
    #pragma unroll
    for (int s = 0; s < 3; s++) {
        float e;
        asm("ex2.approx.f32 %0, %1;" : "=f"(e) : "f"(fmaf(x, c2l, b2l)));
        float r;
        asm("rcp.approx.f32 %0, %1;" : "=f"(r) : "f"(e + 1.0f));
        float u = fmaf(r, -17.0f, 17.5f);
        int   si = (int)u;
        float pos = u - (float)si;
        int bgn = si - 8;
        int end = bgn + 1;
        int bw = bgn < 0 ? bgn + NUM_POINTS : bgn;
        int ew = end < 0 ? end + NUM_POINTS : end;
        float vb = __ldg(&velocity[bw]) * (1.0f / 3.0f);
        float ve = __ldg(&velocity[ew]) * (1.0f / 3.0f);
        float ab = __ldg(&angles[bw]);
        float ae = __ldg(&angles[ew]);
        float velo3 = fmaf(pos, ve - vb, vb);
        float ang   = fmaf(pos, ae - ab, ab);
        float sn, cs;
        __sincosf(ang, &sn, &cs);
        x = fmaf(x, fmaf(velo3, sn, 1.0f), velo3 * cs);
    }
    return x;
}

// ---------------------------------------------------------------------------
// Kernel 2: persistent map, output-driven (identical to R12 best).
// ---------------------------------------------------------------------------
#define MAP_THREADS 1024
#define MAP_BLOCKS  304                   // 2 CTAs resident per SM x 152 SMs
#define TOTAL_O     (32768 * 256)         // 8,388,608 output float4s
#define ILP 4

extern __shared__ float2 s_tab[];

__device__ __forceinline__ float tab_lookup(float x, float c2l, float b2l,
                                            const float* __restrict__ angles,
                                            const float* __restrict__ velocity)
{
    if (fabsf(x) < 4.0f) {
        float t = fmaf(x, TAB_SCALE, 4.0f * TAB_SCALE);   // (x+4)/h
        int   i = (int)t;                                  // 0..8191
        float fr = t - (float)i;
        float2 vd = s_tab[i];                              // one LDS.64
        return fmaf(fr, vd.y, vd.x);
    }
    return f3_exact_g(x, c2l, b2l, angles, velocity);      // ~6e-5 of samples
}

__global__ __launch_bounds__(MAP_THREADS, 2)
void macunit_map_kernel(const float2* __restrict__ data,   // [B*256] float2
                        const float4* __restrict__ att,    // [256] float4
                        const float* __restrict__ angles,
                        const float* __restrict__ velocity,
                        const float* __restrict__ coeff,
                        const float* __restrict__ bias,
                        float4* __restrict__ out)          // [B*256] float4
{
    // Stage pair table into shared memory.
    {
        const float2* gt = g_tab;
        for (int i = threadIdx.x; i < TAB_INTERVALS; i += MAP_THREADS)
            s_tab[i] = __ldg(&gt[i]);
    }
    __syncthreads();

    const float c2l = __ldg(coeff) * 2.8853900817779268f;
    const float b2l = __ldg(bias)  * 2.8853900817779268f;

    const int t0 = blockIdx.x * MAP_THREADS + threadIdx.x;
    const int stride = MAP_BLOCKS * MAP_THREADS;            // 311296 (mult of 256)

    // Loop-invariant attention weights (o & 255 == t0 & 255 for all o).
    const float4 a = __ldg(&att[t0 & 255]);

    int o = t0;
    // Main body: ILP front-batched loads.
    while (o + (ILP - 1) * stride < TOTAL_O) {
        float2 d[ILP];
        #pragma unroll
        for (int k = 0; k < ILP; k++)
            d[k] = __ldg(&data[o + k * stride]);

        #pragma unroll
        for (int k = 0; k < ILP; k++) {
            float y0 = tab_lookup(d[k].x, c2l, b2l, angles, velocity);
            float y1 = tab_lookup(d[k].y, c2l, b2l, angles, velocity);
            float4 ov;
            ov.x = a.x * y0;  ov.y = a.y * y0;
            ov.z = a.z * y1;  ov.w = a.w * y1;
            out[o + k * stride] = ov;
        }
        o += ILP * stride;
    }
    // Tail.
    for (; o < TOTAL_O; o += stride) {
        float2 dv = __ldg(&data[o]);
        float y0 = tab_lookup(dv.x, c2l, b2l, angles, velocity);
        float y1 = tab_lookup(dv.y, c2l, b2l, angles, velocity);
        float4 ov;
        ov.x = a.x * y0;  ov.y = a.y * y0;
        ov.z = a.z * y1;  ov.w = a.w * y1;
        out[o] = ov;
    }
}

extern "C" void kernel_launch(void* const* d_in, const int* in_sizes, int n_in,
                              void* d_out, int out_size)
{
    const float2* data     = (const float2*)d_in[0];  // [32768, 512] f32
    const float*  angles   = (const float*) d_in[1];  // [17]
    const float*  velocity = (const float*) d_in[2];  // [17]
    const float4* att      = (const float4*)d_in[3];  // [1024] f32
    const float*  coeff    = (const float*) d_in[4];  // [1]
    const float*  bias     = (const float*) d_in[5];  // [1]
    float4* out = (float4*)d_out;

    static bool attr_set = false;
    if (!attr_set) {
        cudaFuncSetAttribute(macunit_map_kernel,
                             cudaFuncAttributeMaxDynamicSharedMemorySize,
                             TAB_BYTES);
        attr_set = true;
    }

    build_table_kernel<<<(TAB_INTERVALS + 255) / 256, 256>>>(angles, velocity, coeff, bias);

    macunit_map_kernel<<<MAP_BLOCKS, MAP_THREADS, TAB_BYTES>>>(
        data, att, angles, velocity, coeff, bias, out);
}

// round 15
// speedup vs baseline: 1.0015x; 1.0015x over previous
#include <cuda_runtime.h>

// MacUnit: out[b, 2*ic+k] = attention[2*ic+k] * f3(data[b, ic])
// f3 = 3 iterations of x += step(x)/3 (tanh-indexed piecewise-linear trig).
//
// R15: map kernel loop identical to R12/R14 (35.0us, DRAM 52%). The ~8.8us
// bench-vs-map gap is launch/serialization: map is now launched with
// PROGRAMMATIC DEPENDENT LAUNCH (programmatic stream serialization). Map CTAs
// start while build runs, prefetch their first data batch (table-independent),
// then cudaGridDependencySynchronize() before staging the table from gmem.
// Table: (value,delta) float2, [-4,4], h=1/1024, 64KB smem, 2 CTAs/SM.

#define NUM_POINTS 17
#define TAB_INTERVALS 8192               // h = 1/1024 over [-4,4]
#define TAB_SCALE     1024.0f
#define TAB_H         (1.0f / 1024.0f)
#define TAB_BYTES     (TAB_INTERVALS * 8)   // 65536 B of float2

__device__ float2 g_tab[TAB_INTERVALS];

// ---------------------------------------------------------------------------
// Kernel 1: build (value, delta) pair table. Register-resident segment table
// (lanes 0..17, SHFL lookups) -- no gmem dependency in the eval loop.
// ---------------------------------------------------------------------------
__global__ __launch_bounds__(128)
void build_table_kernel(const float* __restrict__ angles,
                        const float* __restrict__ velocity,
                        const float* __restrict__ coeff,
                        const float* __restrict__ bias)
{
    const int lane = threadIdx.x & 31;

    float r_vb3 = 0.f, r_dv3 = 0.f, r_ab = 0.f, r_da = 0.f;
    if (lane < 18) {
        int bgn = lane - 8;
        int end = bgn + 1;
        int bw = bgn < 0 ? bgn + NUM_POINTS : bgn;    // torch negative wrap
        int ew = end < 0 ? end + NUM_POINTS : end;
        float vb = __ldg(&velocity[bw]) * (1.0f / 3.0f);
        float ve = __ldg(&velocity[ew]) * (1.0f / 3.0f);
        r_vb3 = vb;
        r_dv3 = ve - vb;
        r_ab  = __ldg(&angles[bw]);
        r_da  = __ldg(&angles[ew]) - r_ab;
    }

    const float c2l = __ldg(coeff) * 2.8853900817779268f;   // 2*log2(e)*c
    const float b2l = __ldg(bias)  * 2.8853900817779268f;

    const int i = blockIdx.x * 128 + threadIdx.x;
    if (i >= TAB_INTERVALS) return;

    float v[2];
    #pragma unroll
    for (int q = 0; q < 2; q++) {
        float x = fmaf((float)(i + q), TAB_H, -4.0f);       // exact grid point
        #pragma unroll
        for (int s = 0; s < 3; s++) {
            float e;
            asm("ex2.approx.f32 %0, %1;" : "=f"(e) : "f"(fmaf(x, c2l, b2l)));
            float r;
            asm("rcp.approx.f32 %0, %1;" : "=f"(r) : "f"(e + 1.0f));
            float u = fmaf(r, -17.0f, 17.5f);   // index + 8, in (0.5, 17.5)
            int   si = (int)u;
            float pos = u - (float)si;
            float vb = __shfl_sync(0xffffffffu, r_vb3, si);
            float dv = __shfl_sync(0xffffffffu, r_dv3, si);
            float ab = __shfl_sync(0xffffffffu, r_ab,  si);
            float da = __shfl_sync(0xffffffffu, r_da,  si);
            float velo3 = fmaf(pos, dv, vb);
            float ang   = fmaf(pos, da, ab);
            float sn, cs;
            __sincosf(ang, &sn, &cs);
            x = fmaf(x, fmaf(velo3, sn, 1.0f), velo3 * cs);
        }
        v[q] = x;
    }
    g_tab[i] = make_float2(v[0], v[1] - v[0]);
}

// Exact f3 via gmem tables (rare |x|>=4 path in the map kernel only).
__device__ __forceinline__ float f3_exact_g(float x, float c2l, float b2l,
                                            const float* __restrict__ angles,
                                            const float* __restrict__ velocity)
{
    #pragma unroll
    for (int s = 0; s < 3; s++) {
        float e;
        asm("ex2.approx.f32 %0, %1;" : "=f"(e) : "f"(fmaf(x, c2l, b2l)));
        float r;
        asm("rcp.approx.f32 %0, %1;" : "=f"(r) : "f"(e + 1.0f));
        float u = fmaf(r, -17.0f, 17.5f);
        int   si = (int)u;
        float pos = u - (float)si;
        int bgn = si - 8;
        int end = bgn + 1;
        int bw = bgn < 0 ? bgn + NUM_POINTS : bgn;
        int ew = end < 0 ? end + NUM_POINTS : end;
        float vb = __ldg(&velocity[bw]) * (1.0f / 3.0f);
        float ve = __ldg(&velocity[ew]) * (1.0f / 3.0f);
        float ab = __ldg(&angles[bw]);
        float ae = __ldg(&angles[ew]);
        float velo3 = fmaf(pos, ve - vb, vb);
        float ang   = fmaf(pos, ae - ab, ab);
        float sn, cs;
        __sincosf(ang, &sn, &cs);
        x = fmaf(x, fmaf(velo3, sn, 1.0f), velo3 * cs);
    }
    return x;
}

// ---------------------------------------------------------------------------
// Kernel 2: persistent map, output-driven, PDL-overlapped.
// ---------------------------------------------------------------------------
#define MAP_THREADS 1024
#define MAP_BLOCKS  304                   // 2 CTAs resident per SM x 152 SMs
#define TOTAL_O     (32768 * 256)         // 8,388,608 output float4s
#define ILP 4

extern __shared__ float2 s_tab[];

__device__ __forceinline__ float tab_lookup(float x, float c2l, float b2l,
                                            const float* __restrict__ angles,
                                            const float* __restrict__ velocity)
{
    if (fabsf(x) < 4.0f) {
        float t = fmaf(x, TAB_SCALE, 4.0f * TAB_SCALE);   // (x+4)/h
        int   i = (int)t;                                  // 0..8191
        float fr = t - (float)i;
        float2 vd = s_tab[i];                              // one LDS.64
        return fmaf(fr, vd.y, vd.x);
    }
    return f3_exact_g(x, c2l, b2l, angles, velocity);      // ~6e-5 of samples
}

__global__ __launch_bounds__(MAP_THREADS, 2)
void macunit_map_kernel(const float2* __restrict__ data,   // [B*256] float2
                        const float4* __restrict__ att,    // [256] float4
                        const float* __restrict__ angles,
                        const float* __restrict__ velocity,
                        const float* __restrict__ coeff,
                        const float* __restrict__ bias,
                        float4* __restrict__ out)          // [B*256] float4
{
    const int t0 = blockIdx.x * MAP_THREADS + threadIdx.x;
    const int stride = MAP_BLOCKS * MAP_THREADS;            // 311296 (mult of 256)

    // Prefetch the first data batch BEFORE waiting on the build kernel:
    // these loads are table-independent (always fully valid for iteration 0).
    int o = t0;
    float2 d[ILP];
    #pragma unroll
    for (int k = 0; k < ILP; k++)
        d[k] = __ldg(&data[o + k * stride]);

    // Wait for the build kernel's g_tab writes to be visible.
    cudaGridDependencySynchronize();

    // Stage pair table into shared memory.
    {
        const float2* gt = g_tab;
        for (int i = threadIdx.x; i < TAB_INTERVALS; i += MAP_THREADS)
            s_tab[i] = __ldg(&gt[i]);
    }
    __syncthreads();

    const float c2l = __ldg(coeff) * 2.8853900817779268f;
    const float b2l = __ldg(bias)  * 2.8853900817779268f;

    // Loop-invariant attention weights (o & 255 == t0 & 255 for all o).
    const float4 a = __ldg(&att[t0 & 255]);

    // Main loop: process current batch, then load next (load-at-end keeps
    // register count at the 32-reg cap for 2 CTAs/SM).
    while (true) {
        #pragma unroll
        for (int k = 0; k < ILP; k++) {
            float y0 = tab_lookup(d[k].x, c2l, b2l, angles, velocity);
            float y1 = tab_lookup(d[k].y, c2l, b2l, angles, velocity);
            float4 ov;
            ov.x = a.x * y0;  ov.y = a.y * y0;
            ov.z = a.z * y1;  ov.w = a.w * y1;
            out[o + k * stride] = ov;
        }
        o += ILP * stride;
        if (o + (ILP - 1) * stride < TOTAL_O) {
            #pragma unroll
            for (int k = 0; k < ILP; k++)
                d[k] = __ldg(&data[o + k * stride]);
        } else {
            break;
        }
    }
    // Tail (singles).
    for (; o < TOTAL_O; o += stride) {
        float2 dv = __ldg(&data[o]);
        float y0 = tab_lookup(dv.x, c2l, b2l, angles, velocity);
        float y1 = tab_lookup(dv.y, c2l, b2l, angles, velocity);
        float4 ov;
        ov.x = a.x * y0;  ov.y = a.y * y0;
        ov.z = a.z * y1;  ov.w = a.w * y1;
        out[o] = ov;
    }
}

extern "C" void kernel_launch(void* const* d_in, const int* in_sizes, int n_in,
                              void* d_out, int out_size)
{
    const float2* data     = (const float2*)d_in[0];  // [32768, 512] f32
    const float*  angles   = (const float*) d_in[1];  // [17]
    const float*  velocity = (const float*) d_in[2];  // [17]
    const float4* att      = (const float4*)d_in[3];  // [1024] f32
    const float*  coeff    = (const float*) d_in[4];  // [1]
    const float*  bias     = (const float*) d_in[5];  // [1]
    float4* out = (float4*)d_out;

    static bool attr_set = false;
    if (!attr_set) {
        cudaFuncSetAttribute(macunit_map_kernel,
                             cudaFuncAttributeMaxDynamicSharedMemorySize,
                             TAB_BYTES);
        attr_set = true;
    }

    // Primary: build table.
    build_table_kernel<<<TAB_INTERVALS / 128, 128>>>(angles, velocity, coeff, bias);

    // Secondary: map, launched with programmatic dependent launch so its CTAs
    // spin up (and prefetch data) while the build kernel finishes.
    cudaLaunchConfig_t cfg = {};
    cfg.gridDim  = dim3(MAP_BLOCKS, 1, 1);
    cfg.blockDim = dim3(MAP_THREADS, 1, 1);
    cfg.dynamicSmemBytes = TAB_BYTES;
    cfg.stream = 0;   // legacy default stream (graph capture)
    cudaLaunchAttribute attrs[1];
    attrs[0].id = cudaLaunchAttributeProgrammaticStreamSerialization;
    attrs[0].val.programmaticStreamSerializationAllowed = 1;
    cfg.attrs = attrs;
    cfg.numAttrs = 1;

    cudaLaunchKernelEx(&cfg, macunit_map_kernel,
                       data, att, angles, velocity, coeff, bias, out);
}